// round 1
// baseline (speedup 1.0000x reference)
#include <cuda_runtime.h>

// Problem constants
#define BATCH 8
#define IMH 180
#define IMW 180
#define NF 24
#define KS 5
#define NB 31
#define NPIX (IMH * IMW)          // 32400
#define NTOT (BATCH * NPIX)       // 259200

#define TILE 32
#define UT 40                      // u tile (TILE + 2*4)
#define PT 36                      // phi tile (TILE + 2*2)

__device__ float g_partials[256];
__device__ float g_invM;

// ---------------------------------------------------------------------------
// Stage 1: weighted partial sums for M = mean(u_sigma) + 1e-3.
// sum(u_sigma) = (1/9) * sum_p u[p] * cnt(p), cnt = (3-edge_y)*(3-edge_x).
// Deterministic: fixed per-thread element sets, fixed-order smem tree.
// ---------------------------------------------------------------------------
__global__ void k_part(const float* __restrict__ u) {
    __shared__ float sm[256];
    int tid = threadIdx.x;
    float s = 0.f;
    for (int idx = blockIdx.x * 256 + tid; idx < NTOT; idx += 256 * 256) {
        int p = idx % NPIX;
        int y = p / IMW;
        int x = p - y * IMW;
        float wy = 3.f - (y == 0 ? 1.f : 0.f) - (y == IMH - 1 ? 1.f : 0.f);
        float wx = 3.f - (x == 0 ? 1.f : 0.f) - (x == IMW - 1 ? 1.f : 0.f);
        s += u[idx] * (wy * wx);
    }
    sm[tid] = s;
    __syncthreads();
    for (int o = 128; o > 0; o >>= 1) {
        if (tid < o) sm[tid] += sm[tid + o];
        __syncthreads();
    }
    if (tid == 0) g_partials[blockIdx.x] = sm[0];
}

__global__ void k_fin() {
    __shared__ float sm[256];
    int tid = threadIdx.x;
    sm[tid] = g_partials[tid];
    __syncthreads();
    for (int o = 128; o > 0; o >>= 1) {
        if (tid < o) sm[tid] += sm[tid + o];
        __syncthreads();
    }
    if (tid == 0) {
        float M = sm[0] / (9.f * (float)NTOT) + 0.001f;
        g_invM = 1.f / M;
    }
}

// ---------------------------------------------------------------------------
// Stage 2: fused TNRD stage per 32x32 tile.
// ---------------------------------------------------------------------------
__global__ __launch_bounds__(256) void k_main(
    const float* __restrict__ u,
    const float* __restrict__ f,
    const float* __restrict__ filt,     // [NF,1,5,5]
    const float* __restrict__ lam,
    const float* __restrict__ mu,       // [31]
    const float* __restrict__ wts,      // [31]
    float* __restrict__ out)
{
    __shared__ float sU[UT * UT];       // u tile, origin (oy0-4, ox0-4), 0 outside image
    __shared__ float sUS[PT * PT];      // u_sigma/M on phi tile, origin (oy0-2, ox0-2)
    __shared__ float sPhi[PT * PT];     // scaled_phi for current filter
    __shared__ float sF[NF * 25];
    __shared__ float sMu[NB];
    __shared__ float sW[NB];

    const int b   = blockIdx.z;
    const int oy0 = blockIdx.y * TILE;
    const int ox0 = blockIdx.x * TILE;
    const int tid = threadIdx.x;

    const float* ub = u + b * NPIX;
    const float* fb = f + b * NPIX;
    float* ob = out + b * NPIX;

    // cooperative loads
    for (int i = tid; i < NF * 25; i += 256) sF[i] = filt[i];
    if (tid < NB) { sMu[tid] = mu[tid]; sW[tid] = wts[tid]; }
    for (int i = tid; i < UT * UT; i += 256) {
        int r = i / UT, c = i - r * UT;
        int gy = oy0 - 4 + r, gx = ox0 - 4 + c;
        float v = 0.f;
        if ((unsigned)gy < IMH && (unsigned)gx < IMW) v = ub[gy * IMW + gx];
        sU[i] = v;
    }
    __syncthreads();

    const float invM = g_invM;

    // u_sigma * invM over the phi tile (zero-padded 3x3 sum / 9)
    for (int i = tid; i < PT * PT; i += 256) {
        int r = i / PT, c = i - r * PT;
        float s0 = sU[(r + 1) * UT + c + 1] + sU[(r + 1) * UT + c + 2] + sU[(r + 1) * UT + c + 3];
        float s1 = sU[(r + 2) * UT + c + 1] + sU[(r + 2) * UT + c + 2] + sU[(r + 2) * UT + c + 3];
        float s2 = sU[(r + 3) * UT + c + 1] + sU[(r + 3) * UT + c + 2] + sU[(r + 3) * UT + c + 3];
        sUS[i] = (s0 + s1 + s2) * (1.f / 9.f) * invM;
    }
    __syncthreads();

    float acc0 = 0.f, acc1 = 0.f, acc2 = 0.f, acc3 = 0.f;

    for (int fi = 0; fi < NF; fi++) {
        float F[25];
        #pragma unroll
        for (int j = 0; j < 25; j++) F[j] = sF[fi * 25 + j];

        // forward conv + RBF + scale over phi tile
        for (int i = tid; i < PT * PT; i += 256) {
            int r = i / PT, c = i - r * PT;
            int gy = oy0 - 2 + r, gx = ox0 - 2 + c;
            float val = 0.f;
            if ((unsigned)gy < IMH && (unsigned)gx < IMW) {
                float ca = 0.f, cb = 0.f;
                #pragma unroll
                for (int dy = 0; dy < 5; dy++) {
                    const float* row = &sU[(r + dy) * UT + c];
                    ca = fmaf(row[0], F[dy * 5 + 0], ca);
                    cb = fmaf(row[1], F[dy * 5 + 1], cb);
                    ca = fmaf(row[2], F[dy * 5 + 2], ca);
                    cb = fmaf(row[3], F[dy * 5 + 3], cb);
                    ca = fmaf(row[4], F[dy * 5 + 4], ca);
                }
                float conv = ca + cb;
                // phi(conv) = sum_j w_j * exp(-50*(conv-mu_j)^2)
                float pa = 0.f, pb = 0.f;
                #pragma unroll
                for (int j = 0; j < NB; j += 2) {
                    float d0 = conv - sMu[j];
                    pa = fmaf(sW[j], __expf(-50.f * d0 * d0), pa);
                    if (j + 1 < NB) {
                        float d1 = conv - sMu[j + 1];
                        pb = fmaf(sW[j + 1], __expf(-50.f * d1 * d1), pb);
                    }
                }
                val = sUS[i] * (pa + pb);
            }
            sPhi[i] = val;
        }
        __syncthreads();

        // adjoint conv: diffusion += sum_{dy,dx} sPhi[qy+dy][qx+dx] * F[4-dy][4-dx]
        {
            int q, qy, qx;
            #define ACC_ONE(ACC, K)                                           \
                q = tid + (K) * 256; qy = q >> 5; qx = q & 31;                \
                {                                                             \
                    float a_ = 0.f, b_ = 0.f;                                 \
                    _Pragma("unroll")                                         \
                    for (int dy = 0; dy < 5; dy++) {                          \
                        const float* prow = &sPhi[(qy + dy) * PT + qx];       \
                        const int fb_ = (4 - dy) * 5;                         \
                        a_ = fmaf(prow[0], F[fb_ + 4], a_);                   \
                        b_ = fmaf(prow[1], F[fb_ + 3], b_);                   \
                        a_ = fmaf(prow[2], F[fb_ + 2], a_);                   \
                        b_ = fmaf(prow[3], F[fb_ + 1], b_);                   \
                        a_ = fmaf(prow[4], F[fb_ + 0], a_);                   \
                    }                                                         \
                    ACC += a_ + b_;                                           \
                }
            ACC_ONE(acc0, 0)
            ACC_ONE(acc1, 1)
            ACC_ONE(acc2, 2)
            ACC_ONE(acc3, 3)
            #undef ACC_ONE
        }
        __syncthreads();
    }

    const float lambda = lam[0];
    float accs[4] = {acc0, acc1, acc2, acc3};
    #pragma unroll
    for (int k = 0; k < 4; k++) {
        int q = tid + k * 256;
        int qy = q >> 5, qx = q & 31;
        int gy = oy0 + qy, gx = ox0 + qx;
        if (gy < IMH && gx < IMW) {
            float uv = ub[gy * IMW + gx];
            float fv = fb[gy * IMW + gx];
            float reac = lambda * (uv - fv) / (uv * uv + 1e-3f);
            float o = uv - accs[k] - reac;
            o = fminf(fmaxf(o, 0.f), 1.f);
            ob[gy * IMW + gx] = o;
        }
    }
}

// ---------------------------------------------------------------------------
// Launch
// ---------------------------------------------------------------------------
extern "C" void kernel_launch(void* const* d_in, const int* in_sizes, int n_in,
                              void* d_out, int out_size) {
    const float* u    = (const float*)d_in[0];
    const float* f    = (const float*)d_in[1];
    const float* filt = (const float*)d_in[2];
    const float* lam  = (const float*)d_in[3];
    const float* mu   = (const float*)d_in[4];
    const float* wts  = (const float*)d_in[5];
    float* out = (float*)d_out;

    k_part<<<256, 256>>>(u);
    k_fin<<<1, 256>>>();
    dim3 grid((IMW + TILE - 1) / TILE, (IMH + TILE - 1) / TILE, BATCH);
    k_main<<<grid, 256>>>(u, f, filt, lam, mu, wts, out);
}

// round 2
// speedup vs baseline: 2.6402x; 2.6402x over previous
#include <cuda_runtime.h>

// Problem constants
#define BATCH 8
#define IMH 180
#define IMW 180
#define NF 24
#define KS 5
#define NB 31
#define NPIX (IMH * IMW)          // 32400
#define NTOT (BATCH * NPIX)       // 259200

#define TILE 32
#define UT 40                      // u tile (TILE + 2*4)
#define PT 36                      // phi tile (TILE + 2*2)

// LUT for phi(x) = sum_j w_j exp(-50 (x-mu_j)^2), x in [XMIN, XMAX]
#define NCELL 8192
#define XMIN (-2.0f)
#define XMAX (2.0f)
#define LUT_H ((XMAX - XMIN) / (float)NCELL)
#define LUT_INVH ((float)NCELL / (XMAX - XMIN))

__device__ float  g_partials[64];
__device__ float  g_invM;
__device__ float2 g_lut[NCELL];    // (value at left knot, delta to right knot)

// ---------------------------------------------------------------------------
// LUT build: 8192 cells, exact 31-term RBF at both knots.
// ---------------------------------------------------------------------------
__global__ void k_lut(const float* __restrict__ mu, const float* __restrict__ wts) {
    int i = blockIdx.x * blockDim.x + threadIdx.x;
    if (i >= NCELL) return;
    float x0 = XMIN + (float)i * LUT_H;
    float x1 = x0 + LUT_H;
    float p0 = 0.f, p1 = 0.f;
    #pragma unroll 1
    for (int j = 0; j < NB; j++) {
        float m = mu[j], w = wts[j];
        float d0 = x0 - m, d1 = x1 - m;
        p0 += w * expf(-50.f * d0 * d0);
        p1 += w * expf(-50.f * d1 * d1);
    }
    g_lut[i] = make_float2(p0, p1 - p0);
}

// ---------------------------------------------------------------------------
// Stage 1: weighted partial sums for M = mean(u_sigma) + 1e-3.
// sum(u_sigma)*9 = sum_p u[p]*cnt(p), cnt=(3-edge_y)(3-edge_x). float4 path.
// ---------------------------------------------------------------------------
__global__ void k_part(const float* __restrict__ u) {
    __shared__ float sm[256];
    const int tid = threadIdx.x;
    const float4* u4 = (const float4*)u;
    const int N4 = NTOT / 4;       // 64800, NPIX and IMW divisible by 4
    float s = 0.f;
    for (int i = blockIdx.x * 256 + tid; i < N4; i += 64 * 256) {
        int idx4 = i * 4;
        int p = idx4 % NPIX;
        int y = p / IMW;
        int x0 = p - y * IMW;
        float wy = 3.f - (y == 0 ? 1.f : 0.f) - (y == IMH - 1 ? 1.f : 0.f);
        float4 v = u4[i];
        float w0 = (x0 == 0) ? 2.f : 3.f;
        float w3 = (x0 == IMW - 4) ? 2.f : 3.f;
        s += wy * (v.x * w0 + v.y * 3.f + v.z * 3.f + v.w * w3);
    }
    sm[tid] = s;
    __syncthreads();
    for (int o = 128; o > 0; o >>= 1) {
        if (tid < o) sm[tid] += sm[tid + o];
        __syncthreads();
    }
    if (tid == 0) g_partials[blockIdx.x] = sm[0];
}

__global__ void k_fin() {
    __shared__ float sm[64];
    int tid = threadIdx.x;
    if (tid < 64) sm[tid] = g_partials[tid];
    __syncthreads();
    for (int o = 32; o > 0; o >>= 1) {
        if (tid < o) sm[tid] += sm[tid + o];
        __syncthreads();
    }
    if (tid == 0) {
        float M = sm[0] / (9.f * (float)NTOT) + 0.001f;
        g_invM = 1.f / M;
    }
}

// ---------------------------------------------------------------------------
// Stage 2: fused TNRD stage per 32x32 tile. Dynamic smem layout:
//   [0, 65536)        sLUT  : 8192 x float2
//   [65536, 71936)    sU    : 40x40
//   [71936, 77120)    sUS   : 36x36  (u_sigma/M, zeroed outside image)
//   [77120, 82304)    sPhi  : 36x36
//   [82304, 84704)    sF    : 24x25
// ---------------------------------------------------------------------------
#define SMEM_BYTES 84704

__global__ __launch_bounds__(256) void k_main(
    const float* __restrict__ u,
    const float* __restrict__ f,
    const float* __restrict__ filt,
    const float* __restrict__ lam,
    float* __restrict__ out)
{
    extern __shared__ char smem[];
    float2* sLUT = (float2*)smem;
    float*  sU   = (float*)(smem + 65536);
    float*  sUS  = (float*)(smem + 71936);
    float*  sPhi = (float*)(smem + 77120);
    float*  sF   = (float*)(smem + 82304);

    const int b   = blockIdx.z;
    const int oy0 = blockIdx.y * TILE;
    const int ox0 = blockIdx.x * TILE;
    const int tid = threadIdx.x;

    const float* ub = u + b * NPIX;
    const float* fb = f + b * NPIX;
    float* ob = out + b * NPIX;

    // cooperative loads
    {
        const float4* lg = (const float4*)g_lut;
        float4* ls = (float4*)sLUT;
        #pragma unroll
        for (int k = 0; k < NCELL / 2 / 256; k++)       // 4096 float4 / 256
            ls[tid + k * 256] = lg[tid + k * 256];
    }
    for (int i = tid; i < NF * 25; i += 256) sF[i] = filt[i];
    for (int i = tid; i < UT * UT; i += 256) {
        int r = i / UT, c = i - r * UT;
        int gy = oy0 - 4 + r, gx = ox0 - 4 + c;
        float v = 0.f;
        if ((unsigned)gy < IMH && (unsigned)gx < IMW) v = ub[gy * IMW + gx];
        sU[i] = v;
    }
    __syncthreads();

    const float invM = g_invM;

    // u_sigma/M on phi tile; zero at out-of-image positions (bakes the mask in)
    for (int i = tid; i < PT * PT; i += 256) {
        int r = i / PT, c = i - r * PT;
        int gy = oy0 - 2 + r, gx = ox0 - 2 + c;
        float v = 0.f;
        if ((unsigned)gy < IMH && (unsigned)gx < IMW) {
            float s0 = sU[(r + 1) * UT + c + 1] + sU[(r + 1) * UT + c + 2] + sU[(r + 1) * UT + c + 3];
            float s1 = sU[(r + 2) * UT + c + 1] + sU[(r + 2) * UT + c + 2] + sU[(r + 2) * UT + c + 3];
            float s2 = sU[(r + 3) * UT + c + 1] + sU[(r + 3) * UT + c + 2] + sU[(r + 3) * UT + c + 3];
            v = (s0 + s1 + s2) * (1.f / 9.f) * invM;
        }
        sUS[i] = v;
    }
    __syncthreads();

    // adjoint strip for this thread: 1x4 outputs, fixed across all filters
    const int qy = tid >> 3;              // 0..31
    const int qc0 = (tid & 7) * 4;        // 0..28
    float acc0 = 0.f, acc1 = 0.f, acc2 = 0.f, acc3 = 0.f;

    for (int fi = 0; fi < NF; fi++) {
        float F[25];
        #pragma unroll
        for (int j = 0; j < 25; j++) F[j] = sF[fi * 25 + j];

        // ---- forward conv + LUT phi + scale, 1x4 strips over 36x36 ----
        for (int t = tid; t < (PT / 4) * PT; t += 256) {   // 324 tasks
            int r = t / 9, c0 = (t - r * 9) * 4;
            float s0 = 0.f, s1 = 0.f, s2 = 0.f, s3 = 0.f;
            #pragma unroll
            for (int dy = 0; dy < 5; dy++) {
                const float4* row = (const float4*)&sU[(r + dy) * UT + c0];
                float4 A = row[0];
                float4 Bv = row[1];
                const float* Fr = &F[dy * 5];
                s0 = fmaf(A.x, Fr[0], s0); s1 = fmaf(A.y, Fr[0], s1);
                s2 = fmaf(A.z, Fr[0], s2); s3 = fmaf(A.w, Fr[0], s3);
                s0 = fmaf(A.y, Fr[1], s0); s1 = fmaf(A.z, Fr[1], s1);
                s2 = fmaf(A.w, Fr[1], s2); s3 = fmaf(Bv.x, Fr[1], s3);
                s0 = fmaf(A.z, Fr[2], s0); s1 = fmaf(A.w, Fr[2], s1);
                s2 = fmaf(Bv.x, Fr[2], s2); s3 = fmaf(Bv.y, Fr[2], s3);
                s0 = fmaf(A.w, Fr[3], s0); s1 = fmaf(Bv.x, Fr[3], s1);
                s2 = fmaf(Bv.y, Fr[3], s2); s3 = fmaf(Bv.z, Fr[3], s3);
                s0 = fmaf(Bv.x, Fr[4], s0); s1 = fmaf(Bv.y, Fr[4], s1);
                s2 = fmaf(Bv.z, Fr[4], s2); s3 = fmaf(Bv.w, Fr[4], s3);
            }
            float4 ph;
            {
                float conv[4] = {s0, s1, s2, s3};
                float res[4];
                #pragma unroll
                for (int k = 0; k < 4; k++) {
                    float xc = fminf(fmaxf(conv[k], XMIN), XMAX);
                    float tt = (xc - XMIN) * LUT_INVH;
                    int ii = (int)tt;
                    ii = min(ii, NCELL - 1);
                    float frac = tt - (float)ii;
                    float2 cell = sLUT[ii];
                    float phi = fmaf(cell.y, frac, cell.x);
                    res[k] = sUS[r * PT + c0 + k] * phi;
                }
                ph = make_float4(res[0], res[1], res[2], res[3]);
            }
            *(float4*)&sPhi[r * PT + c0] = ph;
        }
        __syncthreads();

        // ---- adjoint conv (flipped filter), 1x4 strip per thread ----
        {
            float a0 = 0.f, a1 = 0.f, a2 = 0.f, a3 = 0.f;
            #pragma unroll
            for (int dy = 0; dy < 5; dy++) {
                const float4* row = (const float4*)&sPhi[(qy + dy) * PT + qc0];
                float4 A = row[0];
                float4 Bv = row[1];
                const float* Fr = &F[(4 - dy) * 5];
                a0 = fmaf(A.x, Fr[4], a0); a1 = fmaf(A.y, Fr[4], a1);
                a2 = fmaf(A.z, Fr[4], a2); a3 = fmaf(A.w, Fr[4], a3);
                a0 = fmaf(A.y, Fr[3], a0); a1 = fmaf(A.z, Fr[3], a1);
                a2 = fmaf(A.w, Fr[3], a2); a3 = fmaf(Bv.x, Fr[3], a3);
                a0 = fmaf(A.z, Fr[2], a0); a1 = fmaf(A.w, Fr[2], a1);
                a2 = fmaf(Bv.x, Fr[2], a2); a3 = fmaf(Bv.y, Fr[2], a3);
                a0 = fmaf(A.w, Fr[1], a0); a1 = fmaf(Bv.x, Fr[1], a1);
                a2 = fmaf(Bv.y, Fr[1], a2); a3 = fmaf(Bv.z, Fr[1], a3);
                a0 = fmaf(Bv.x, Fr[0], a0); a1 = fmaf(Bv.y, Fr[0], a1);
                a2 = fmaf(Bv.z, Fr[0], a2); a3 = fmaf(Bv.w, Fr[0], a3);
            }
            acc0 += a0; acc1 += a1; acc2 += a2; acc3 += a3;
        }
        __syncthreads();
    }

    // ---- epilogue: reaction + clip ----
    const float lambda = lam[0];
    const int gy = oy0 + qy;
    if (gy < IMH) {
        float accs[4] = {acc0, acc1, acc2, acc3};
        #pragma unroll
        for (int k = 0; k < 4; k++) {
            int gx = ox0 + qc0 + k;
            if (gx < IMW) {
                float uv = ub[gy * IMW + gx];
                float fv = fb[gy * IMW + gx];
                float reac = lambda * (uv - fv) / (uv * uv + 1e-3f);
                float o = uv - accs[k] - reac;
                o = fminf(fmaxf(o, 0.f), 1.f);
                ob[gy * IMW + gx] = o;
            }
        }
    }
}

// ---------------------------------------------------------------------------
// Launch
// ---------------------------------------------------------------------------
extern "C" void kernel_launch(void* const* d_in, const int* in_sizes, int n_in,
                              void* d_out, int out_size) {
    const float* u    = (const float*)d_in[0];
    const float* f    = (const float*)d_in[1];
    const float* filt = (const float*)d_in[2];
    const float* lam  = (const float*)d_in[3];
    const float* mu   = (const float*)d_in[4];
    const float* wts  = (const float*)d_in[5];
    float* out = (float*)d_out;

    static bool attr_set = false;
    if (!attr_set) {
        cudaFuncSetAttribute(k_main, cudaFuncAttributeMaxDynamicSharedMemorySize,
                             SMEM_BYTES);
        attr_set = true;
    }

    k_lut<<<(NCELL + 255) / 256, 256>>>(mu, wts);
    k_part<<<64, 256>>>(u);
    k_fin<<<1, 64>>>();
    dim3 grid((IMW + TILE - 1) / TILE, (IMH + TILE - 1) / TILE, BATCH);
    k_main<<<grid, 256, SMEM_BYTES>>>(u, f, filt, lam, out);
}

// round 3
// speedup vs baseline: 2.9130x; 1.1033x over previous
#include <cuda_runtime.h>

// Problem constants
#define BATCH 8
#define IMH 180
#define IMW 180
#define NF 24
#define KS 5
#define NB 31
#define NPIX (IMH * IMW)          // 32400
#define NTOT (BATCH * NPIX)       // 259200
#define N4   (NTOT / 4)           // 64800

#define TILE 32
#define UT 40                      // u tile (TILE + 2*4)
#define PT 36                      // phi tile (TILE + 2*2)

// LUT for phi(x) = sum_j w_j exp(-50 (x-mu_j)^2), x in [XMIN, XMAX]
#define NCELL 8192
#define XMIN (-2.0f)
#define XMAX (2.0f)
#define LUT_H ((XMAX - XMIN) / (float)NCELL)
#define LUT_INVH ((float)NCELL / (XMAX - XMIN))

#define NTHR 352                   // 11 warps; 324 forward tasks, 256 adjoint tasks

__device__ float  g_partials[256];
__device__ float  g_invM;
__device__ float2 g_lut[NCELL];

// ---------------------------------------------------------------------------
// k_init: blocks [0,32) build the LUT; blocks [32, 288) compute weighted
// partial sums for M = mean(u_sigma)+1e-3 (one float4 per thread).
// sum(u_sigma)*9 = sum_p u[p]*cnt(p), cnt=(3-edge_y)(3-edge_x).
// ---------------------------------------------------------------------------
__global__ void k_init(const float* __restrict__ u,
                       const float* __restrict__ mu,
                       const float* __restrict__ wts) {
    const int tid = threadIdx.x;
    if (blockIdx.x < 32) {
        int i = blockIdx.x * 256 + tid;        // 0..8191
        float x0 = XMIN + (float)i * LUT_H;
        float x1 = x0 + LUT_H;
        float p0 = 0.f, p1 = 0.f;
        #pragma unroll 1
        for (int j = 0; j < NB; j++) {
            float m = mu[j], w = wts[j];
            float d0 = x0 - m, d1 = x1 - m;
            p0 += w * expf(-50.f * d0 * d0);
            p1 += w * expf(-50.f * d1 * d1);
        }
        g_lut[i] = make_float2(p0, p1 - p0);
    } else {
        __shared__ float sm[256];
        const int pb = blockIdx.x - 32;        // 0..255
        const int i = pb * 256 + tid;
        float s = 0.f;
        if (i < N4) {
            int idx4 = i * 4;
            int p = idx4 % NPIX;
            int y = p / IMW;
            int x0 = p - y * IMW;
            float wy = 3.f - (y == 0 ? 1.f : 0.f) - (y == IMH - 1 ? 1.f : 0.f);
            float4 v = ((const float4*)u)[i];
            float w0 = (x0 == 0) ? 2.f : 3.f;
            float w3 = (x0 == IMW - 4) ? 2.f : 3.f;
            s = wy * (v.x * w0 + v.y * 3.f + v.z * 3.f + v.w * w3);
        }
        sm[tid] = s;
        __syncthreads();
        for (int o = 128; o > 0; o >>= 1) {
            if (tid < o) sm[tid] += sm[tid + o];
            __syncthreads();
        }
        if (tid == 0) g_partials[pb] = sm[0];
    }
}

__global__ void k_fin() {
    __shared__ float sm[256];
    int tid = threadIdx.x;
    sm[tid] = g_partials[tid];
    __syncthreads();
    for (int o = 128; o > 0; o >>= 1) {
        if (tid < o) sm[tid] += sm[tid + o];
        __syncthreads();
    }
    if (tid == 0) {
        float M = sm[0] / (9.f * (float)NTOT) + 0.001f;
        g_invM = 1.f / M;
    }
}

// ---------------------------------------------------------------------------
// k_main: fused TNRD stage per 32x32 tile.
// Dynamic smem layout:
//   [0, 65536)         sLUT  : 8192 x float2
//   [65536, 71936)     sU    : 40x40
//   [71936, 77120)     sUS   : 36x36  (u_sigma/M, zeroed outside image)
//   [77120, 82304)     sPhi0 : 36x36
//   [82304, 87488)     sPhi1 : 36x36
//   [87488, 89888)     sF    : 24x25
// ---------------------------------------------------------------------------
#define SMEM_BYTES 89888

__global__ __launch_bounds__(NTHR, 2) void k_main(
    const float* __restrict__ u,
    const float* __restrict__ f,
    const float* __restrict__ filt,
    const float* __restrict__ lam,
    float* __restrict__ out)
{
    extern __shared__ char smem[];
    float2* sLUT  = (float2*)smem;
    float*  sU    = (float*)(smem + 65536);
    float*  sUS   = (float*)(smem + 71936);
    float*  sPhi0 = (float*)(smem + 77120);
    float*  sPhi1 = (float*)(smem + 82304);
    float*  sF    = (float*)(smem + 87488);

    const int b   = blockIdx.z;
    const int oy0 = blockIdx.y * TILE;
    const int ox0 = blockIdx.x * TILE;
    const int tid = threadIdx.x;

    const float* ub = u + b * NPIX;
    const float* fb = f + b * NPIX;
    float* ob = out + b * NPIX;

    // cooperative loads
    {
        const float4* lg = (const float4*)g_lut;
        float4* ls = (float4*)sLUT;
        for (int i = tid; i < NCELL / 2; i += NTHR)   // 4096 float4
            ls[i] = lg[i];
    }
    for (int i = tid; i < NF * 25; i += NTHR) sF[i] = filt[i];
    for (int i = tid; i < UT * UT; i += NTHR) {
        int r = i / UT, c = i - r * UT;
        int gy = oy0 - 4 + r, gx = ox0 - 4 + c;
        float v = 0.f;
        if ((unsigned)gy < IMH && (unsigned)gx < IMW) v = ub[gy * IMW + gx];
        sU[i] = v;
    }
    __syncthreads();

    const float invM = g_invM;

    // u_sigma/M on phi tile; zero outside image (bakes the mask in)
    for (int i = tid; i < PT * PT; i += NTHR) {
        int r = i / PT, c = i - r * PT;
        int gy = oy0 - 2 + r, gx = ox0 - 2 + c;
        float v = 0.f;
        if ((unsigned)gy < IMH && (unsigned)gx < IMW) {
            float s0 = sU[(r + 1) * UT + c + 1] + sU[(r + 1) * UT + c + 2] + sU[(r + 1) * UT + c + 3];
            float s1 = sU[(r + 2) * UT + c + 1] + sU[(r + 2) * UT + c + 2] + sU[(r + 2) * UT + c + 3];
            float s2 = sU[(r + 3) * UT + c + 1] + sU[(r + 3) * UT + c + 2] + sU[(r + 3) * UT + c + 3];
            v = (s0 + s1 + s2) * (1.f / 9.f) * invM;
        }
        sUS[i] = v;
    }
    __syncthreads();

    // ---- fixed per-thread task assignments ----
    // forward: tid < 324 handles phi strip (fr, fc0..fc0+3)
    const int fr  = tid / 9;
    const int fc0 = (tid - fr * 9) * 4;
    const bool fwd_on = (tid < 324);
    // adjoint: tid < 256 handles output strip (qy, qc0..qc0+3)
    const int qy  = tid >> 3;
    const int qc0 = (tid & 7) * 4;
    const bool adj_on = (tid < 256);

    // register cache of the 5x8 u window for this thread's forward strip
    float4 UA[5], UB[5];
    float4 usvec = make_float4(0.f, 0.f, 0.f, 0.f);
    if (fwd_on) {
        #pragma unroll
        for (int dy = 0; dy < 5; dy++) {
            const float4* row = (const float4*)&sU[(fr + dy) * UT + fc0];
            UA[dy] = row[0];
            UB[dy] = row[1];
        }
        usvec = *(const float4*)&sUS[fr * PT + fc0];
    }

    float acc0 = 0.f, acc1 = 0.f, acc2 = 0.f, acc3 = 0.f;

    // forward conv + LUT phi + scale, entirely from registers (except LUT/sUS)
    #define FORWARD(DSTBUF, FARR)                                             \
        {                                                                     \
            float s0 = 0.f, s1 = 0.f, s2 = 0.f, s3 = 0.f;                     \
            _Pragma("unroll")                                                 \
            for (int dy = 0; dy < 5; dy++) {                                  \
                float4 A = UA[dy];                                            \
                float4 Bv = UB[dy];                                           \
                const float* Fr = &FARR[dy * 5];                              \
                s0 = fmaf(A.x, Fr[0], s0); s1 = fmaf(A.y, Fr[0], s1);         \
                s2 = fmaf(A.z, Fr[0], s2); s3 = fmaf(A.w, Fr[0], s3);         \
                s0 = fmaf(A.y, Fr[1], s0); s1 = fmaf(A.z, Fr[1], s1);         \
                s2 = fmaf(A.w, Fr[1], s2); s3 = fmaf(Bv.x, Fr[1], s3);        \
                s0 = fmaf(A.z, Fr[2], s0); s1 = fmaf(A.w, Fr[2], s1);         \
                s2 = fmaf(Bv.x, Fr[2], s2); s3 = fmaf(Bv.y, Fr[2], s3);       \
                s0 = fmaf(A.w, Fr[3], s0); s1 = fmaf(Bv.x, Fr[3], s1);        \
                s2 = fmaf(Bv.y, Fr[3], s2); s3 = fmaf(Bv.z, Fr[3], s3);       \
                s0 = fmaf(Bv.x, Fr[4], s0); s1 = fmaf(Bv.y, Fr[4], s1);       \
                s2 = fmaf(Bv.z, Fr[4], s2); s3 = fmaf(Bv.w, Fr[4], s3);       \
            }                                                                 \
            float conv[4] = {s0, s1, s2, s3};                                 \
            float usv[4] = {usvec.x, usvec.y, usvec.z, usvec.w};              \
            float res[4];                                                     \
            _Pragma("unroll")                                                 \
            for (int k = 0; k < 4; k++) {                                     \
                float xc = fminf(fmaxf(conv[k], XMIN), XMAX);                 \
                float tt = (xc - XMIN) * LUT_INVH;                            \
                int ii = (int)tt;                                             \
                ii = min(ii, NCELL - 1);                                      \
                float frac = tt - (float)ii;                                  \
                float2 cell = sLUT[ii];                                       \
                res[k] = usv[k] * fmaf(cell.y, frac, cell.x);                 \
            }                                                                 \
            *(float4*)&DSTBUF[fr * PT + fc0] =                                \
                make_float4(res[0], res[1], res[2], res[3]);                  \
        }

    // adjoint conv: taps via broadcast LDS from sF (flipped kernel)
    #define ADJOINT(SRCBUF, FI)                                               \
        {                                                                     \
            float a0 = 0.f, a1 = 0.f, a2 = 0.f, a3 = 0.f;                     \
            const float* Fs = &sF[(FI) * 25];                                 \
            _Pragma("unroll")                                                 \
            for (int dy = 0; dy < 5; dy++) {                                  \
                const float4* row = (const float4*)&SRCBUF[(qy + dy) * PT + qc0]; \
                float4 A = row[0];                                            \
                float4 Bv = row[1];                                           \
                const float* Fr = &Fs[(4 - dy) * 5];                          \
                a0 = fmaf(A.x, Fr[4], a0); a1 = fmaf(A.y, Fr[4], a1);         \
                a2 = fmaf(A.z, Fr[4], a2); a3 = fmaf(A.w, Fr[4], a3);         \
                a0 = fmaf(A.y, Fr[3], a0); a1 = fmaf(A.z, Fr[3], a1);         \
                a2 = fmaf(A.w, Fr[3], a2); a3 = fmaf(Bv.x, Fr[3], a3);        \
                a0 = fmaf(A.z, Fr[2], a0); a1 = fmaf(A.w, Fr[2], a1);         \
                a2 = fmaf(Bv.x, Fr[2], a2); a3 = fmaf(Bv.y, Fr[2], a3);       \
                a0 = fmaf(A.w, Fr[1], a0); a1 = fmaf(Bv.x, Fr[1], a1);        \
                a2 = fmaf(Bv.y, Fr[1], a2); a3 = fmaf(Bv.z, Fr[1], a3);       \
                a0 = fmaf(Bv.x, Fr[0], a0); a1 = fmaf(Bv.y, Fr[0], a1);       \
                a2 = fmaf(Bv.z, Fr[0], a2); a3 = fmaf(Bv.w, Fr[0], a3);       \
            }                                                                 \
            acc0 += a0; acc1 += a1; acc2 += a2; acc3 += a3;                   \
        }

    // software pipeline: forward(f+1) overlaps adjoint(f); 1 sync per filter
    float F[25];
    #pragma unroll
    for (int j = 0; j < 25; j++) F[j] = sF[j];
    if (fwd_on) FORWARD(sPhi0, F)
    __syncthreads();

    #pragma unroll 1
    for (int fi = 0; fi < NF; fi++) {
        const int nxt = fi + 1;
        if (nxt < NF) {
            #pragma unroll
            for (int j = 0; j < 25; j++) F[j] = sF[nxt * 25 + j];
            if (fwd_on) {
                if (nxt & 1) { FORWARD(sPhi1, F) } else { FORWARD(sPhi0, F) }
            }
        }
        if (adj_on) {
            if (fi & 1) { ADJOINT(sPhi1, fi) } else { ADJOINT(sPhi0, fi) }
        }
        __syncthreads();
    }
    #undef FORWARD
    #undef ADJOINT

    // ---- epilogue: reaction + clip (u from smem) ----
    if (adj_on) {
        const float lambda = lam[0];
        const int gy = oy0 + qy;
        float accs[4] = {acc0, acc1, acc2, acc3};
        float4 uv4 = *(const float4*)&sU[(qy + 4) * UT + qc0 + 4];
        float uvs[4] = {uv4.x, uv4.y, uv4.z, uv4.w};
        if (gy < IMH) {
            #pragma unroll
            for (int k = 0; k < 4; k++) {
                int gx = ox0 + qc0 + k;
                if (gx < IMW) {
                    float uv = uvs[k];
                    float fv = fb[gy * IMW + gx];
                    float reac = lambda * (uv - fv) / (uv * uv + 1e-3f);
                    float o = uv - accs[k] - reac;
                    o = fminf(fmaxf(o, 0.f), 1.f);
                    ob[gy * IMW + gx] = o;
                }
            }
        }
    }
}

// ---------------------------------------------------------------------------
// Launch
// ---------------------------------------------------------------------------
extern "C" void kernel_launch(void* const* d_in, const int* in_sizes, int n_in,
                              void* d_out, int out_size) {
    const float* u    = (const float*)d_in[0];
    const float* f    = (const float*)d_in[1];
    const float* filt = (const float*)d_in[2];
    const float* lam  = (const float*)d_in[3];
    const float* mu   = (const float*)d_in[4];
    const float* wts  = (const float*)d_in[5];
    float* out = (float*)d_out;

    static bool attr_set = false;
    if (!attr_set) {
        cudaFuncSetAttribute(k_main, cudaFuncAttributeMaxDynamicSharedMemorySize,
                             SMEM_BYTES);
        attr_set = true;
    }

    k_init<<<288, 256>>>(u, mu, wts);
    k_fin<<<1, 256>>>();
    dim3 grid((IMW + TILE - 1) / TILE, (IMH + TILE - 1) / TILE, BATCH);
    k_main<<<grid, NTHR, SMEM_BYTES>>>(u, f, filt, lam, out);
}